// round 12
// baseline (speedup 1.0000x reference)
#include <cuda_runtime.h>
#include <cstddef>

// LSTM: B=64, S=1024, I=256, H=512. out = [h_T (64x512), c_T (64x512)].
//
// Persistent kernel: 128 blocks (all co-resident at occ 1), 256 threads each.
// Block owns 4 hidden units x 4 gates = 16 output columns of the fused
// [4H, K=768] weight matrix. W lives in REGISTERS, packed as f32x2 pairs:
// each lane owns (1 column, 48-wide K segment) = 24 x 64-bit regs.
// Mainloop: broadcast LDS.128 of v = [x_t | h_t] + packed fma.rn.f32x2
// (FFMA2: 2 FMA/issue; ptxas never emits it from C++, PTX-only). Tied "+l"
// accumulator constraint keeps it in-place (no compiler MOV64 restore).
//
// Pipelined staging: batch tile bt only reads vsh rows bt*16..bt*16+15, so
// after the grid barrier only h-chunk 0 (16 batches) is staged serially;
// h-chunk bt+1 and x[t+1]-chunk bt are prefetched into registers during
// tile bt's FFMA2 mainloop and stored to smem once tile bt's reads are done.
// Gate gather via __shfl_sync; cell state in registers (bt loop unrolled).
// Grid sync: monotonic ticket barrier (graph-replay safe, no reset needed).
// (Audited 5x + harness-interaction check; held stable pending first datapoint.)

#define NBLK 128
#define NTHR 256
#define HID  512
#define INP  256
#define KTOT 768
#define BATCH 64
#define SEQ  1024
#define COLS 16      // output cols per block (4 gates x 4 hid units)
#define PCOLS 17     // padded partials stride (kills 2-way bank conflicts)
#define KSEG 16      // K split factor
#define KC   48      // K per segment (16*48 = 768)
#define BT   16      // batch tile
#define NBT  (BATCH/BT)

// smem: vsh [64][768] staged v, part [16][16][17] K-partials, bias [16]
#define SMEM_FLOATS (BATCH*KTOT + KSEG*BT*PCOLS + COLS)
#define SMEM_BYTES  (SMEM_FLOATS*4)

__device__ __align__(256) float g_hbuf[2][BATCH][HID];
__device__ unsigned long long g_ctr;   // monotonic; base always % NBLK == 0

// Tied accumulator: FFMA2 Rd, Ra, Rb, Rd -- no separate output allocation.
#define FFMA2(acc, w, v) \
    asm("fma.rn.f32x2 %0, %1, %2, %0;" : "+l"(acc) : "l"(w), "l"(v))

struct LstmParams {
    const float* x;
    const float* Wx[4];
    const float* bx[4];
    const float* Wh[4];
    const float* bh[4];
    float* out;
};

__device__ __forceinline__ void grid_barrier() {
    __syncthreads();
    if (threadIdx.x == 0) {
        __threadfence();   // release this block's h writes
        unsigned long long t = atomicAdd(&g_ctr, 1ULL) + 1ULL;
        unsigned long long target = ((t + (NBLK - 1)) / NBLK) * NBLK;
        while (*(volatile unsigned long long*)&g_ctr < target) __nanosleep(16);
        __threadfence();   // acquire side
    }
    __syncthreads();
}

__global__ void __launch_bounds__(NTHR, 1) lstm_kernel(LstmParams p) {
    extern __shared__ __align__(16) float smem[];
    float* vsh  = smem;                     // [BATCH][KTOT]
    float* part = vsh + BATCH * KTOT;       // [KSEG][BT][PCOLS]
    float* bsm  = part + KSEG * BT * PCOLS; // [COLS]

    const int tid  = threadIdx.x;
    const int blk  = blockIdx.x;
    const int l    = tid & 31;
    const int c    = l & 15;                        // column within block
    const int kseg = ((tid >> 5) << 1) | (l >> 4);  // 16 K-segs over 8 warps
    const int gate = c >> 2;
    const int hidx = c & 3;
    const int hid0 = blk * 4;
    const int hid  = hid0 + hidx;
    const int kbase = kseg * KC;

    // ---- persistent packed weight registers: 24 x f32x2 covering 48 K ----
    unsigned long long w2[KC / 2];
    {
        const float* Wxg = p.Wx[gate];
        const float* Whg = p.Wh[gate];
        float wr[KC];
        #pragma unroll
        for (int k = 0; k < KC; k++) {
            int kk = kbase + k;
            wr[k] = (kk < INP) ? Wxg[hid * INP + kk]
                               : Whg[hid * HID + (kk - INP)];
        }
        #pragma unroll
        for (int j = 0; j < KC / 2; j++)
            w2[j] = (unsigned long long)__float_as_uint(wr[2 * j])
                  | ((unsigned long long)__float_as_uint(wr[2 * j + 1]) << 32);
    }

    if (tid < COLS) {
        int g = tid >> 2, hx = tid & 3;
        bsm[tid] = p.bx[g][hid0 + hx] + p.bh[g][hid0 + hx];
    }

    // ---- prologue: stage x[0]; zero h region of vsh (h0 = 0) ----
    #pragma unroll
    for (int i = 0; i < 16; i++) {
        int f = tid + NTHR * i;        // 0..4095 float4s of x[:,0,:]
        int b = f >> 6, c4 = f & 63;
        float4 v = __ldg((const float4*)(p.x + ((size_t)b * SEQ) * INP + c4 * 4));
        *(float4*)(vsh + b * KTOT + c4 * 4) = v;
    }
    #pragma unroll
    for (int i = 0; i < 32; i++) {
        int f = tid + NTHR * i;        // 0..8191 float4s of h region
        int b = f >> 7, c4 = f & 127;
        *(float4*)(vsh + b * KTOT + INP + c4 * 4) = make_float4(0.f, 0.f, 0.f, 0.f);
    }

    float creg[NBT] = {0.f, 0.f, 0.f, 0.f};   // cell state (held by cc<4 threads)

    for (int t = 0; t < SEQ; t++) {
        const int cur = t & 1, nxt = cur ^ 1;

        if (t > 0) {
            // stage ONLY h-chunk 0 (batches 0..15) serially; rest pipelined
            #pragma unroll
            for (int i = 0; i < 8; i++) {
                int f = tid + NTHR * i;            // 0..2047
                int b = f >> 7, c4 = f & 127;
                float4 v = __ldcg((const float4*)(&g_hbuf[cur][b][c4 * 4]));
                *(float4*)(vsh + b * KTOT + INP + c4 * 4) = v;
            }
        }
        __syncthreads();

        #pragma unroll
        for (int bt = 0; bt < NBT; bt++) {
            // prefetch x[t+1] chunk bt (no recurrence dep)
            float4 xpre[4];
            if (t + 1 < SEQ) {
                #pragma unroll
                for (int j = 0; j < 4; j++) {
                    int f = tid + NTHR * j;
                    int bl = f >> 6, c4 = f & 63;
                    int b = bt * BT + bl;
                    xpre[j] = __ldg((const float4*)(p.x + ((size_t)b * SEQ + (t + 1)) * INP + c4 * 4));
                }
            }
            // prefetch h[t] chunk bt+1 (covered by this tile's FMA latency)
            float4 hpre[8];
            if (t > 0 && bt + 1 < NBT) {
                #pragma unroll
                for (int i = 0; i < 8; i++) {
                    int f = tid + NTHR * i;
                    int bl = f >> 7, c4 = f & 127;
                    int b = (bt + 1) * BT + bl;
                    hpre[i] = __ldcg((const float4*)(&g_hbuf[cur][b][c4 * 4]));
                }
            }

            // ---- FFMA2 mainloop: 12 x 16 iterations, 2 packed FMAs each ----
            unsigned long long acc2[BT];
            #pragma unroll
            for (int b = 0; b < BT; b++) acc2[b] = 0ULL;

            const float* vbase = vsh + (bt * BT) * KTOT + kbase;
            #pragma unroll
            for (int j = 0; j < KC / 4; j++) {
                #pragma unroll
                for (int b = 0; b < BT; b++) {
                    ulonglong2 v2 = *(const ulonglong2*)(vbase + b * KTOT + j * 4);
                    FFMA2(acc2[b], w2[2 * j],     v2.x);
                    FFMA2(acc2[b], w2[2 * j + 1], v2.y);
                }
            }

            #pragma unroll
            for (int b = 0; b < BT; b++) {
                float lo = __uint_as_float((unsigned)(acc2[b] & 0xFFFFFFFFu));
                float hi = __uint_as_float((unsigned)(acc2[b] >> 32));
                part[(kseg * BT + b) * PCOLS + c] = lo + hi;
            }
            __syncthreads();   // partials visible; tile bt's vsh reads done

            // store prefetched x[t+1] rows (tile bt rows: reads done)
            if (t + 1 < SEQ) {
                #pragma unroll
                for (int j = 0; j < 4; j++) {
                    int f = tid + NTHR * j;
                    int bl = f >> 6, c4 = f & 63;
                    *(float4*)(vsh + (bt * BT + bl) * KTOT + c4 * 4) = xpre[j];
                }
            }
            // store prefetched h[t] into chunk bt+1 rows (not yet read this
            // step; next read is tile bt+1's compute, after loop-end sync)
            if (t > 0 && bt + 1 < NBT) {
                #pragma unroll
                for (int i = 0; i < 8; i++) {
                    int f = tid + NTHR * i;
                    int bl = f >> 7, c4 = f & 127;
                    *(float4*)(vsh + ((bt + 1) * BT + bl) * KTOT + INP + c4 * 4) = hpre[i];
                }
            }

            // ---- reduce over K-segments + activation + cell update ----
            {
                int bl = tid >> 4, cc = tid & 15;   // batch row, column
                float s = bsm[cc];
                #pragma unroll
                for (int ks = 0; ks < KSEG; ks++)
                    s += part[(ks * BT + bl) * PCOLS + cc];
                float a;
                if (cc < 12) a = 1.f / (1.f + __expf(-s));   // gates i, f, o
                else         a = tanhf(s);                    // gate g (cell cand)

                // lanes cc<4 gather f/o/g for (bl, hidx=cc) from lanes
                // gb16 + cc + {4,8,12} of the same 16-lane group
                const unsigned mask = 0xFFFFFFFFu;
                const int gb16 = l & 16;
                float fg = __shfl_sync(mask, a, gb16 + ((cc + 4)  & 15));
                float og = __shfl_sync(mask, a, gb16 + ((cc + 8)  & 15));
                float gg = __shfl_sync(mask, a, gb16 + ((cc + 12) & 15));

                if (cc < 4) {
                    float ig   = a;               // own value: gate i, hidx=cc
                    float cold = creg[bt];
                    float cnew = fmaf(fg, cold, ig * gg);
                    float hnew = og * tanhf(cnew);
                    creg[bt] = cnew;
                    int bg = bt * BT + bl;
                    g_hbuf[nxt][bg][hid0 + cc] = hnew;
                    if (t == SEQ - 1) {
                        p.out[bg * HID + hid0 + cc]               = hnew;  // h_T
                        p.out[BATCH * HID + bg * HID + hid0 + cc] = cnew;  // c_T
                    }
                }
            }
            __syncthreads();   // part consumed + h-chunk bt+1 visible
        }

        if (t < SEQ - 1) grid_barrier();
    }
}

extern "C" void kernel_launch(void* const* d_in, const int* in_sizes, int n_in,
                              void* d_out, int out_size) {
    LstmParams p;
    p.x = (const float*)d_in[0];
    for (int g = 0; g < 4; g++) {
        p.Wx[g] = (const float*)d_in[1 + 4 * g];
        p.bx[g] = (const float*)d_in[2 + 4 * g];
        p.Wh[g] = (const float*)d_in[3 + 4 * g];
        p.bh[g] = (const float*)d_in[4 + 4 * g];
    }
    p.out = (float*)d_out;
    cudaFuncSetAttribute(lstm_kernel, cudaFuncAttributeMaxDynamicSharedMemorySize, SMEM_BYTES);
    lstm_kernel<<<NBLK, NTHR, SMEM_BYTES>>>(p);
}

// round 17
// speedup vs baseline: 1.2336x; 1.2336x over previous
#include <cuda_runtime.h>
#include <cstddef>

// LSTM: B=64, S=1024, I=256, H=512. out = [h_T (64x512), c_T (64x512)].
//
// R12 post-mortem: regs=255 (spills) was the bottleneck -- register prefetch
// of h/x staging (48 regs of arrays) pushed ptxas over the cliff; L1=56.8%
// was spill LDL/STL traffic, fma pipe starved at 22%.
// Fix: all staging now via cp.async (LDGSTS, GMEM->SMEM, ZERO register cost):
//   - h[t] staged as 4 commit-groups (one per 16-batch chunk) issued right
//     after the grid barrier;
//   - x[t+1] chunk bt issued as one group after tile bt's reads complete;
//   - before each tile: cp.async.wait_group 3 + __syncthreads. With the fixed
//     issue order (h0..h3, x0..x3 per step; commit always executed), allowing
//     the 3 newest groups to stay pending completes exactly the chunk needed.
// R14 fix: mainloop restored to FULL #pragma unroll -- the partial "unroll 4"
// left j runtime-variable, making w2[2*j] a dynamically-indexed register
// array (forced local-memory demotion = the same spill disease).
// Mainloop: broadcast LDS.128 + packed fma.rn.f32x2 (FFMA2, tied "+l"
// accumulator), weights register-resident (24 x 64-bit per lane).
// Grid sync: monotonic ticket barrier (graph-replay safe, no reset).
// (Held byte-stable pending first bench of the cp.async build.)

#define NBLK 128
#define NTHR 256
#define HID  512
#define INP  256
#define KTOT 768
#define BATCH 64
#define SEQ  1024
#define COLS 16      // output cols per block (4 gates x 4 hid units)
#define PCOLS 17     // padded partials stride (kills 2-way bank conflicts)
#define KSEG 16      // K split factor
#define KC   48      // K per segment (16*48 = 768)
#define BT   16      // batch tile
#define NBT  (BATCH/BT)

// smem: vsh [64][768] staged v, part [16][16][17] K-partials, bias [16]
#define SMEM_FLOATS (BATCH*KTOT + KSEG*BT*PCOLS + COLS)
#define SMEM_BYTES  (SMEM_FLOATS*4)

__device__ __align__(256) float g_hbuf[2][BATCH][HID];
__device__ unsigned long long g_ctr;   // monotonic; base always % NBLK == 0

// Tied accumulator: FFMA2 Rd, Ra, Rb, Rd -- no separate output allocation.
#define FFMA2(acc, w, v) \
    asm("fma.rn.f32x2 %0, %1, %2, %0;" : "+l"(acc) : "l"(w), "l"(v))

// cp.async: 16B GMEM->SMEM, L1-bypass (.cg), zero register residency.
#define CP_ASYNC16(smem_u32, gptr) \
    asm volatile("cp.async.cg.shared.global [%0], [%1], 16;" \
                 :: "r"(smem_u32), "l"(gptr))
#define CP_COMMIT() asm volatile("cp.async.commit_group;" ::: "memory")
#define CP_WAIT3()  asm volatile("cp.async.wait_group 3;"  ::: "memory")

struct LstmParams {
    const float* x;
    const float* Wx[4];
    const float* bx[4];
    const float* Wh[4];
    const float* bh[4];
    float* out;
};

__device__ __forceinline__ void grid_barrier() {
    __syncthreads();
    if (threadIdx.x == 0) {
        __threadfence();   // release this block's h writes
        unsigned long long t = atomicAdd(&g_ctr, 1ULL) + 1ULL;
        unsigned long long target = ((t + (NBLK - 1)) / NBLK) * NBLK;
        while (*(volatile unsigned long long*)&g_ctr < target) __nanosleep(16);
        __threadfence();   // acquire side
    }
    __syncthreads();
}

__global__ void __launch_bounds__(NTHR, 1) lstm_kernel(LstmParams p) {
    extern __shared__ __align__(16) float smem[];
    float* vsh  = smem;                     // [BATCH][KTOT]
    float* part = vsh + BATCH * KTOT;       // [KSEG][BT][PCOLS]
    float* bsm  = part + KSEG * BT * PCOLS; // [COLS]
    const unsigned vsh_u32 = (unsigned)__cvta_generic_to_shared(vsh);

    const int tid  = threadIdx.x;
    const int blk  = blockIdx.x;
    const int l    = tid & 31;
    const int c    = l & 15;                        // column within block
    const int kseg = ((tid >> 5) << 1) | (l >> 4);  // 16 K-segs over 8 warps
    const int gate = c >> 2;
    const int hidx = c & 3;
    const int hid0 = blk * 4;
    const int hid  = hid0 + hidx;
    const int kbase = kseg * KC;

    // ---- persistent packed weight registers: 24 x f32x2 covering 48 K ----
    unsigned long long w2[KC / 2];
    {
        const float* Wxg = p.Wx[gate];
        const float* Whg = p.Wh[gate];
        float wr[KC];
        #pragma unroll
        for (int k = 0; k < KC; k++) {
            int kk = kbase + k;
            wr[k] = (kk < INP) ? Wxg[hid * INP + kk]
                               : Whg[hid * HID + (kk - INP)];
        }
        #pragma unroll
        for (int j = 0; j < KC / 2; j++)
            w2[j] = (unsigned long long)__float_as_uint(wr[2 * j])
                  | ((unsigned long long)__float_as_uint(wr[2 * j + 1]) << 32);
    }

    if (tid < COLS) {
        int g = tid >> 2, hx = tid & 3;
        bsm[tid] = p.bx[g][hid0 + hx] + p.bh[g][hid0 + hx];
    }

    // ---- prologue: stage x[0]; zero h region of vsh (h0 = 0) ----
    #pragma unroll
    for (int i = 0; i < 16; i++) {
        int f = tid + NTHR * i;        // 0..4095 float4s of x[:,0,:]
        int b = f >> 6, c4 = f & 63;
        float4 v = __ldg((const float4*)(p.x + ((size_t)b * SEQ) * INP + c4 * 4));
        *(float4*)(vsh + b * KTOT + c4 * 4) = v;
    }
    #pragma unroll
    for (int i = 0; i < 32; i++) {
        int f = tid + NTHR * i;        // 0..8191 float4s of h region
        int b = f >> 7, c4 = f & 127;
        *(float4*)(vsh + b * KTOT + INP + c4 * 4) = make_float4(0.f, 0.f, 0.f, 0.f);
    }

    float creg[NBT] = {0.f, 0.f, 0.f, 0.f};   // cell state (held by cc<4 threads)

    for (int t = 0; t < SEQ; t++) {
        const int cur = t & 1, nxt = cur ^ 1;

        // issue h[t] staging: 4 cp.async commit-groups, one per batch chunk
        if (t > 0) {
            #pragma unroll
            for (int ch = 0; ch < NBT; ch++) {
                #pragma unroll
                for (int i = 0; i < 8; i++) {
                    int f   = tid + NTHR * i;        // 0..2047
                    int row = ch * BT + (f >> 7);    // batch row
                    int c16 = f & 127;               // 16B unit within 2KB row
                    CP_ASYNC16(vsh_u32 + (unsigned)(row * KTOT + INP + c16 * 4) * 4u,
                               &g_hbuf[cur][row][c16 * 4]);
                }
                CP_COMMIT();
            }
        }

        #pragma unroll
        for (int bt = 0; bt < NBT; bt++) {
            // complete every group except the 3 newest: finishes h-chunk bt
            // (and, at bt==0, all of last step's x groups)
            CP_WAIT3();
            __syncthreads();

            // ---- FFMA2 mainloop: 12 x 16 iterations, 2 packed FMAs each ----
            unsigned long long acc2[BT];
            #pragma unroll
            for (int b = 0; b < BT; b++) acc2[b] = 0ULL;

            const float* vbase = vsh + (bt * BT) * KTOT + kbase;
            #pragma unroll
            for (int j = 0; j < KC / 4; j++) {
                #pragma unroll
                for (int b = 0; b < BT; b++) {
                    ulonglong2 v2 = *(const ulonglong2*)(vbase + b * KTOT + j * 4);
                    FFMA2(acc2[b], w2[2 * j],     v2.x);
                    FFMA2(acc2[b], w2[2 * j + 1], v2.y);
                }
            }

            #pragma unroll
            for (int b = 0; b < BT; b++) {
                float lo = __uint_as_float((unsigned)(acc2[b] & 0xFFFFFFFFu));
                float hi = __uint_as_float((unsigned)(acc2[b] >> 32));
                part[(kseg * BT + b) * PCOLS + c] = lo + hi;
            }
            __syncthreads();   // partials visible; tile bt's vsh reads done

            // issue x[t+1] chunk bt (rows just consumed; read next step).
            // CP_COMMIT unconditional to keep group counting uniform.
            if (t + 1 < SEQ) {
                #pragma unroll
                for (int j = 0; j < 4; j++) {
                    int f   = tid + NTHR * j;        // 0..1023
                    int row = bt * BT + (f >> 6);    // batch row
                    int c16 = f & 63;                // 16B unit within 1KB row
                    CP_ASYNC16(vsh_u32 + (unsigned)(row * KTOT + c16 * 4) * 4u,
                               p.x + ((size_t)row * SEQ + (t + 1)) * INP + c16 * 4);
                }
            }
            CP_COMMIT();

            // ---- reduce over K-segments + activation + cell update ----
            {
                int bl = tid >> 4, cc = tid & 15;   // batch row, column
                float s = bsm[cc];
                #pragma unroll
                for (int ks = 0; ks < KSEG; ks++)
                    s += part[(ks * BT + bl) * PCOLS + cc];
                float a;
                if (cc < 12) a = 1.f / (1.f + __expf(-s));   // gates i, f, o
                else         a = tanhf(s);                    // gate g (cell cand)

                // lanes cc<4 gather f/o/g for (bl, hidx=cc) from lanes
                // gb16 + cc + {4,8,12} of the same 16-lane group
                const unsigned mask = 0xFFFFFFFFu;
                const int gb16 = l & 16;
                float fg = __shfl_sync(mask, a, gb16 + ((cc + 4)  & 15));
                float og = __shfl_sync(mask, a, gb16 + ((cc + 8)  & 15));
                float gg = __shfl_sync(mask, a, gb16 + ((cc + 12) & 15));

                if (cc < 4) {
                    float ig   = a;               // own value: gate i, hidx=cc
                    float cold = creg[bt];
                    float cnew = fmaf(fg, cold, ig * gg);
                    float hnew = og * tanhf(cnew);
                    creg[bt] = cnew;
                    int bg = bt * BT + bl;
                    g_hbuf[nxt][bg][hid0 + cc] = hnew;
                    if (t == SEQ - 1) {
                        p.out[bg * HID + hid0 + cc]               = hnew;  // h_T
                        p.out[BATCH * HID + bg * HID + hid0 + cc] = cnew;  // c_T
                    }
                }
            }
            // next tile's CP_WAIT3 + __syncthreads separates part reuse
        }

        if (t < SEQ - 1) grid_barrier();
    }
}

extern "C" void kernel_launch(void* const* d_in, const int* in_sizes, int n_in,
                              void* d_out, int out_size) {
    LstmParams p;
    p.x = (const float*)d_in[0];
    for (int g = 0; g < 4; g++) {
        p.Wx[g] = (const float*)d_in[1 + 4 * g];
        p.bx[g] = (const float*)d_in[2 + 4 * g];
        p.Wh[g] = (const float*)d_in[3 + 4 * g];
        p.bh[g] = (const float*)d_in[4 + 4 * g];
    }
    p.out = (float*)d_out;
    cudaFuncSetAttribute(lstm_kernel, cudaFuncAttributeMaxDynamicSharedMemorySize, SMEM_BYTES);
    lstm_kernel<<<NBLK, NTHR, SMEM_BYTES>>>(p);
}